// round 1
// baseline (speedup 1.0000x reference)
#include <cuda_runtime.h>

#define N_   16
#define C_   256
#define CM_  64
#define H_   96
#define W_   96
#define HW_  9216   // 96*96

// ---------------- scratch (device globals; no allocations) ----------------
__device__ float g_mean[N_ * C_];               // spatial means of x
__device__ float g_wdyn[N_ * CM_ * 25];         // dynamic 5x5 weights
__device__ float g_watr[N_ * CM_ * 9];          // dynamic 3x3 (dil=2) weights
__device__ float g_f  [N_ * CM_ * HW_];         // f = relu(1x1 conv)
__device__ float g_dw0[N_ * CM_ * HW_];         // depthwise 5x5 branch
__device__ float g_dw1[N_ * CM_ * HW_];         // depthwise 3x3 atrous branch

// ---------------- kernel 1: per-(n,c) spatial mean of x ----------------
__global__ __launch_bounds__(256) void mean_kernel(const float* __restrict__ x) {
    int nc = blockIdx.x;                        // 0..N*C-1
    const float4* p4 = (const float4*)(x + (size_t)nc * HW_);
    float s = 0.f;
    for (int i = threadIdx.x; i < HW_ / 4; i += 256) {
        float4 v = p4[i];
        s += v.x + v.y + v.z + v.w;
    }
    for (int o = 16; o > 0; o >>= 1) s += __shfl_down_sync(0xffffffffu, s, o);
    __shared__ float sm[8];
    if ((threadIdx.x & 31) == 0) sm[threadIdx.x >> 5] = s;
    __syncthreads();
    if (threadIdx.x == 0) {
        float tot = 0.f;
        #pragma unroll
        for (int i = 0; i < 8; i++) tot += sm[i];
        g_mean[nc] = tot * (1.0f / (float)HW_);
    }
}

// ---------------- kernel 2: g + dynamic depthwise weights ----------------
__global__ __launch_bounds__(256) void weights_kernel(
    const float* __restrict__ conv_w, const float* __restrict__ conv_b,
    const float* __restrict__ ckw,  const float* __restrict__ ckb,
    const float* __restrict__ ck2w, const float* __restrict__ ck2b,
    const float* __restrict__ kw,   const float* __restrict__ kb,
    const float* __restrict__ k2w,  const float* __restrict__ k2b)
{
    __shared__ float sm[C_];
    int n = blockIdx.x;
    int t = threadIdx.x;
    sm[t] = g_mean[n * C_ + t];
    __syncthreads();
    int warp = t >> 5, lane = t & 31;
    float a1 = ckw[0],  b1 = ckb[0];
    float a2 = ck2w[0], b2 = ck2b[0];
    for (int c = warp; c < CM_; c += 8) {
        float s = 0.f;
        #pragma unroll
        for (int kk = 0; kk < 8; kk++)
            s += sm[lane + kk * 32] * conv_w[c * C_ + lane + kk * 32];
        #pragma unroll
        for (int o = 16; o > 0; o >>= 1) s += __shfl_xor_sync(0xffffffffu, s, o);
        float g = fmaxf(s + conv_b[c], 0.f);
        int idx = n * CM_ + c;
        if (lane < 25) g_wdyn[idx * 25 + lane] = fmaf(a1, fmaf(g, kw[lane],  kb[lane]),  b1);
        if (lane < 9)  g_watr[idx * 9  + lane] = fmaf(a2, fmaf(g, k2w[lane], k2b[lane]), b2);
    }
}

// ---------------- kernel 3: 1x1 conv C->Cm + ReLU (register-tiled GEMM) ----------------
// Block: 128 pixels of one image, all 64 outputs. Thread (to,tp): 4 outs x 8 px.
__global__ __launch_bounds__(256) void conv1_kernel(
    const float* __restrict__ x,
    const float* __restrict__ conv_w,
    const float* __restrict__ conv_b)
{
    __shared__ float wch[32][65];   // current K-chunk of weights, transposed [k][o]
    __shared__ float xs[32][128];   // x tile [k][px]
    int t = threadIdx.x;
    int n = blockIdx.y;
    int base = blockIdx.x * 128;
    const float* xp = x + (size_t)n * C_ * HW_ + base;
    int to = t >> 4;   // 0..15 -> outputs to*4 .. to*4+3
    int tp = t & 15;   // pixels tp*8 .. tp*8+7

    float acc[4][8];
    #pragma unroll
    for (int a = 0; a < 4; a++)
        #pragma unroll
        for (int b = 0; b < 8; b++) acc[a][b] = 0.f;

    for (int kc = 0; kc < 8; kc++) {
        // load x tile: 32 channels x 128 px
        #pragma unroll
        for (int i = 0; i < 16; i++) {
            int idx = t + i * 256;
            int r = idx >> 7, cc = idx & 127;
            xs[r][cc] = xp[(size_t)(kc * 32 + r) * HW_ + cc];
        }
        // load weight chunk transposed: wch[k][o] = conv_w[o][kc*32+k]
        #pragma unroll
        for (int i = 0; i < 8; i++) {
            int idx = t + i * 256;
            int o = idx >> 5, k = idx & 31;
            wch[k][o] = conv_w[o * C_ + kc * 32 + k];
        }
        __syncthreads();
        #pragma unroll
        for (int k = 0; k < 32; k++) {
            float w0 = wch[k][to * 4 + 0];
            float w1 = wch[k][to * 4 + 1];
            float w2 = wch[k][to * 4 + 2];
            float w3 = wch[k][to * 4 + 3];
            float4 xv0 = *(const float4*)&xs[k][tp * 8];
            float4 xv1 = *(const float4*)&xs[k][tp * 8 + 4];
            float xv[8] = {xv0.x, xv0.y, xv0.z, xv0.w, xv1.x, xv1.y, xv1.z, xv1.w};
            #pragma unroll
            for (int b = 0; b < 8; b++) {
                acc[0][b] = fmaf(w0, xv[b], acc[0][b]);
                acc[1][b] = fmaf(w1, xv[b], acc[1][b]);
                acc[2][b] = fmaf(w2, xv[b], acc[2][b]);
                acc[3][b] = fmaf(w3, xv[b], acc[3][b]);
            }
        }
        __syncthreads();
    }

    float* fp = g_f + (size_t)n * CM_ * HW_ + base;
    #pragma unroll
    for (int a = 0; a < 4; a++) {
        int o = to * 4 + a;
        float bv = conv_b[o];
        float4 r0, r1;
        r0.x = fmaxf(acc[a][0] + bv, 0.f);
        r0.y = fmaxf(acc[a][1] + bv, 0.f);
        r0.z = fmaxf(acc[a][2] + bv, 0.f);
        r0.w = fmaxf(acc[a][3] + bv, 0.f);
        r1.x = fmaxf(acc[a][4] + bv, 0.f);
        r1.y = fmaxf(acc[a][5] + bv, 0.f);
        r1.z = fmaxf(acc[a][6] + bv, 0.f);
        r1.w = fmaxf(acc[a][7] + bv, 0.f);
        *(float4*)&fp[(size_t)o * HW_ + tp * 8]     = r0;
        *(float4*)&fp[(size_t)o * HW_ + tp * 8 + 4] = r1;
    }
}

// ---------------- kernel 4: both dynamic depthwise convs ----------------
// Block: one (n, c, 8-row chunk). smem halo tile 12x100.
__global__ __launch_bounds__(256) void dw_kernel(
    const float* __restrict__ adap_b, const float* __restrict__ atrous_b)
{
    __shared__ float sf[12][100];
    __shared__ float sw[25];
    __shared__ float swa[9];
    int t  = threadIdx.x;
    int rc = blockIdx.x;   // 0..11 (8-row chunks)
    int c  = blockIdx.y;   // 0..63
    int n  = blockIdx.z;   // 0..15
    int r0 = rc * 8;
    const float* fp = g_f + ((size_t)n * CM_ + c) * HW_;

    for (int idx = t; idx < 1200; idx += 256) {
        int i = idx / 100, j = idx - i * 100;
        int gr = r0 - 2 + i, gc = j - 2;
        float v = 0.f;
        if (gr >= 0 && gr < H_ && gc >= 0 && gc < W_) v = fp[gr * W_ + gc];
        sf[i][j] = v;
    }
    if (t < 25) sw[t]  = g_wdyn[((size_t)n * CM_ + c) * 25 + t];
    if (t < 9)  swa[t] = g_watr[((size_t)n * CM_ + c) * 9  + t];
    __syncthreads();

    float ab  = adap_b[c];
    float atb = atrous_b[c];
    float* o0 = g_dw0 + ((size_t)n * CM_ + c) * HW_;
    float* o1 = g_dw1 + ((size_t)n * CM_ + c) * HW_;

    #pragma unroll
    for (int q = 0; q < 3; q++) {
        int px = t + q * 256;          // 0..767
        int r = px / 96, col = px - r * 96;
        float s5 = 0.f;
        #pragma unroll
        for (int i = 0; i < 5; i++)
            #pragma unroll
            for (int j = 0; j < 5; j++)
                s5 = fmaf(sw[i * 5 + j], sf[r + i][col + j], s5);
        float s3 = 0.f;
        #pragma unroll
        for (int i = 0; i < 3; i++)
            #pragma unroll
            for (int j = 0; j < 3; j++)
                s3 = fmaf(swa[i * 3 + j], sf[r + 2 * i][col + 2 * j], s3);
        o0[(r0 + r) * W_ + col] = s5 + ab;
        o1[(r0 + r) * W_ + col] = s3 + atb;
    }
}

// ---------------- kernel 5: fuse GEMM per branch -> d_out ----------------
// Block: 128 pixels, 128 outputs, K=64. Thread (to,tp): 8 outs x 8 px.
__global__ __launch_bounds__(256) void fuse_kernel(
    float* __restrict__ out,
    const float* __restrict__ fuse_w,
    const float* __restrict__ fuse_b)
{
    __shared__ float ws[128 * 64];   // fuse_w copied as-is [o][c]
    __shared__ float ds[16][128];    // dw tile chunk [c][px]
    int t = threadIdx.x;
    int n = blockIdx.y;
    int br = blockIdx.z;             // 0: 5x5 branch, 1: atrous branch
    int base = blockIdx.x * 128;
    const float* dwp = (br ? g_dw1 : g_dw0) + (size_t)n * CM_ * HW_ + base;

    for (int i = t; i < 128 * 64; i += 256) ws[i] = fuse_w[i];

    int to = t >> 4;   // 0..15 -> outputs to*8 .. to*8+7
    int tp = t & 15;   // pixels tp*8 .. tp*8+7
    float acc[8][8];
    #pragma unroll
    for (int a = 0; a < 8; a++)
        #pragma unroll
        for (int b = 0; b < 8; b++) acc[a][b] = 0.f;

    for (int cc = 0; cc < 4; cc++) {
        #pragma unroll
        for (int i = 0; i < 8; i++) {
            int idx = t + i * 256;
            int cl = idx >> 7, px = idx & 127;
            ds[cl][px] = dwp[(size_t)(cc * 16 + cl) * HW_ + px];
        }
        __syncthreads();
        #pragma unroll
        for (int kl = 0; kl < 16; kl++) {
            int k = cc * 16 + kl;
            float4 xv0 = *(const float4*)&ds[kl][tp * 8];
            float4 xv1 = *(const float4*)&ds[kl][tp * 8 + 4];
            float xv[8] = {xv0.x, xv0.y, xv0.z, xv0.w, xv1.x, xv1.y, xv1.z, xv1.w};
            #pragma unroll
            for (int a = 0; a < 8; a++) {
                float w = ws[(to * 8 + a) * 64 + k];
                #pragma unroll
                for (int b = 0; b < 8; b++)
                    acc[a][b] = fmaf(w, xv[b], acc[a][b]);
            }
        }
        __syncthreads();
    }

    float* yp = out + ((size_t)n * 256 + br * 128) * HW_ + base;
    #pragma unroll
    for (int a = 0; a < 8; a++) {
        int o = to * 8 + a;
        float bv = fuse_b[o];
        float4 r0, r1;
        r0.x = acc[a][0] + bv; r0.y = acc[a][1] + bv;
        r0.z = acc[a][2] + bv; r0.w = acc[a][3] + bv;
        r1.x = acc[a][4] + bv; r1.y = acc[a][5] + bv;
        r1.z = acc[a][6] + bv; r1.w = acc[a][7] + bv;
        *(float4*)&yp[(size_t)o * HW_ + tp * 8]     = r0;
        *(float4*)&yp[(size_t)o * HW_ + tp * 8 + 4] = r1;
    }
}

// ---------------- launcher ----------------
extern "C" void kernel_launch(void* const* d_in, const int* in_sizes, int n_in,
                              void* d_out, int out_size) {
    const float* x        = (const float*)d_in[0];
    const float* conv_w   = (const float*)d_in[1];
    const float* conv_b   = (const float*)d_in[2];
    const float* ckw      = (const float*)d_in[3];   // conv_k_w (scalar)
    const float* ckb      = (const float*)d_in[4];   // conv_k_b
    const float* ck2w     = (const float*)d_in[5];   // conv_k2_w
    const float* ck2b     = (const float*)d_in[6];   // conv_k2_b
    const float* kw       = (const float*)d_in[7];   // conv_kernel_w (25)
    const float* kb       = (const float*)d_in[8];   // conv_kernel_b (25)
    const float* k2w      = (const float*)d_in[9];   // conv_kernel2_w (9)
    const float* k2b      = (const float*)d_in[10];  // conv_kernel2_b (9)
    const float* fuse_w   = (const float*)d_in[11];  // (128,64)
    const float* fuse_b   = (const float*)d_in[12];  // (128)
    const float* adap_b   = (const float*)d_in[13];  // (64)
    const float* atrous_b = (const float*)d_in[14];  // (64)
    float* out = (float*)d_out;

    mean_kernel<<<N_ * C_, 256>>>(x);
    weights_kernel<<<N_, 256>>>(conv_w, conv_b, ckw, ckb, ck2w, ck2b, kw, kb, k2w, k2b);
    conv1_kernel<<<dim3(HW_ / 128, N_), 256>>>(x, conv_w, conv_b);
    dw_kernel<<<dim3(12, CM_, N_), 256>>>(adap_b, atrous_b);
    fuse_kernel<<<dim3(HW_ / 128, N_, 2), 256>>>(out, fuse_w, fuse_b);
}

// round 2
// speedup vs baseline: 1.8216x; 1.8216x over previous
#include <cuda_runtime.h>
#include <cstdint>

#define N_   16
#define C_   256
#define CM_  64
#define H_   96
#define W_   96
#define HW_  9216   // 96*96

// ---------------- scratch (device globals; no allocations) ----------------
__device__ float g_mean[N_ * C_];
__device__ float g_wdyn[N_ * CM_ * 25];
__device__ float g_watr[N_ * CM_ * 9];
__device__ float g_f  [N_ * CM_ * HW_];
__device__ float g_dw0[N_ * CM_ * HW_];
__device__ float g_dw1[N_ * CM_ * HW_];

// ---------------- tf32 helpers ----------------
__device__ __forceinline__ float f2tf(float f) {
    uint32_t r;
    asm("cvt.rna.tf32.f32 %0, %1;" : "=r"(r) : "f"(f));
    return __uint_as_float(r);
}

__device__ __forceinline__ void mma8(float* d, const uint32_t* a, uint32_t b0, uint32_t b1) {
    asm volatile(
        "mma.sync.aligned.m16n8k8.row.col.f32.tf32.tf32.f32 "
        "{%0,%1,%2,%3},{%4,%5,%6,%7},{%8,%9},{%0,%1,%2,%3};\n"
        : "+f"(d[0]), "+f"(d[1]), "+f"(d[2]), "+f"(d[3])
        : "r"(a[0]), "r"(a[1]), "r"(a[2]), "r"(a[3]), "r"(b0), "r"(b1));
}

// ---------------- kernel 1: per-(n,c) spatial mean of x ----------------
__global__ __launch_bounds__(256) void mean_kernel(const float* __restrict__ x) {
    int nc = blockIdx.x;
    const float4* p4 = (const float4*)(x + (size_t)nc * HW_);
    float s = 0.f;
    for (int i = threadIdx.x; i < HW_ / 4; i += 256) {
        float4 v = p4[i];
        s += v.x + v.y + v.z + v.w;
    }
    for (int o = 16; o > 0; o >>= 1) s += __shfl_down_sync(0xffffffffu, s, o);
    __shared__ float sm[8];
    if ((threadIdx.x & 31) == 0) sm[threadIdx.x >> 5] = s;
    __syncthreads();
    if (threadIdx.x == 0) {
        float tot = 0.f;
        #pragma unroll
        for (int i = 0; i < 8; i++) tot += sm[i];
        g_mean[nc] = tot * (1.0f / (float)HW_);
    }
}

// ---------------- kernel 2: g + dynamic depthwise weights ----------------
__global__ __launch_bounds__(256) void weights_kernel(
    const float* __restrict__ conv_w, const float* __restrict__ conv_b,
    const float* __restrict__ ckw,  const float* __restrict__ ckb,
    const float* __restrict__ ck2w, const float* __restrict__ ck2b,
    const float* __restrict__ kw,   const float* __restrict__ kb,
    const float* __restrict__ k2w,  const float* __restrict__ k2b)
{
    __shared__ float sm[C_];
    int n = blockIdx.x;
    int t = threadIdx.x;
    sm[t] = g_mean[n * C_ + t];
    __syncthreads();
    int warp = t >> 5, lane = t & 31;
    float a1 = ckw[0],  b1 = ckb[0];
    float a2 = ck2w[0], b2 = ck2b[0];
    for (int c = warp; c < CM_; c += 8) {
        float s = 0.f;
        #pragma unroll
        for (int kk = 0; kk < 8; kk++)
            s += sm[lane + kk * 32] * conv_w[c * C_ + lane + kk * 32];
        #pragma unroll
        for (int o = 16; o > 0; o >>= 1) s += __shfl_xor_sync(0xffffffffu, s, o);
        float g = fmaxf(s + conv_b[c], 0.f);
        int idx = n * CM_ + c;
        if (lane < 25) g_wdyn[idx * 25 + lane] = fmaf(a1, fmaf(g, kw[lane],  kb[lane]),  b1);
        if (lane < 9)  g_watr[idx * 9  + lane] = fmaf(a2, fmaf(g, k2w[lane], k2b[lane]), b2);
    }
}

// ---------------- kernel 3: 1x1 conv via tf32 mma ----------------
// Block tile: 128 px (M) x 64 outs (N), K=256 in slabs of 32.
// 8 warps: wm=warp&3 -> 32-px strip, wn=warp>>2 -> 32-out strip.
__global__ __launch_bounds__(256) void conv1_mma(
    const float* __restrict__ x,
    const float* __restrict__ conv_w,
    const float* __restrict__ conv_b)
{
    __shared__ float sm[8448];
    float* xs = sm;              // [32][136]  A: xs[k][px]
    float* wt = sm + 32 * 136;   // [32][72]   B: wt[k][o]
    int t = threadIdx.x, lane = t & 31, warp = t >> 5;
    int gq = lane >> 2, gr = lane & 3;
    int n = blockIdx.y;
    int base = blockIdx.x * 128;
    int wm = warp & 3, wn = warp >> 2;
    const float* xp = x + (size_t)n * C_ * HW_ + base;

    float acc[2][4][4];
    #pragma unroll
    for (int a = 0; a < 2; a++)
        #pragma unroll
        for (int b = 0; b < 4; b++)
            #pragma unroll
            for (int c = 0; c < 4; c++) acc[a][b][c] = 0.f;

    for (int slab = 0; slab < 8; ++slab) {
        #pragma unroll
        for (int i = 0; i < 4; ++i) {
            int idx = t + i * 256;
            int r = idx >> 5, c4 = idx & 31;
            float4 v = *(const float4*)(xp + (size_t)(slab * 32 + r) * HW_ + c4 * 4);
            float4 w;
            w.x = f2tf(v.x); w.y = f2tf(v.y); w.z = f2tf(v.z); w.w = f2tf(v.w);
            *(float4*)(xs + r * 136 + c4 * 4) = w;
        }
        #pragma unroll
        for (int i = 0; i < 8; ++i) {
            int idx = t + i * 256;
            int k = idx & 31, o = idx >> 5;
            wt[k * 72 + o] = f2tf(conv_w[o * C_ + slab * 32 + k]);
        }
        __syncthreads();
        #pragma unroll
        for (int kk = 0; kk < 4; ++kk) {
            int k0 = kk * 8;
            uint32_t a[2][4];
            #pragma unroll
            for (int mt = 0; mt < 2; ++mt) {
                int px = wm * 32 + mt * 16 + gq;
                a[mt][0] = __float_as_uint(xs[(k0 + gr) * 136 + px]);
                a[mt][1] = __float_as_uint(xs[(k0 + gr) * 136 + px + 8]);
                a[mt][2] = __float_as_uint(xs[(k0 + gr + 4) * 136 + px]);
                a[mt][3] = __float_as_uint(xs[(k0 + gr + 4) * 136 + px + 8]);
            }
            #pragma unroll
            for (int nt = 0; nt < 4; ++nt) {
                int o = wn * 32 + nt * 8 + gq;
                uint32_t b0 = __float_as_uint(wt[(k0 + gr) * 72 + o]);
                uint32_t b1 = __float_as_uint(wt[(k0 + gr + 4) * 72 + o]);
                mma8(acc[0][nt], a[0], b0, b1);
                mma8(acc[1][nt], a[1], b0, b1);
            }
        }
        __syncthreads();
    }

    // stage per-warp 32px x 32out tile -> coalesced channel-major writes
    float* st = sm + warp * 1056;  // 32*33
    #pragma unroll
    for (int mt = 0; mt < 2; ++mt)
        #pragma unroll
        for (int nt = 0; nt < 4; ++nt) {
            int pr = mt * 16 + gq, oc = nt * 8 + 2 * gr;
            st[pr * 33 + oc]           = acc[mt][nt][0];
            st[pr * 33 + oc + 1]       = acc[mt][nt][1];
            st[(pr + 8) * 33 + oc]     = acc[mt][nt][2];
            st[(pr + 8) * 33 + oc + 1] = acc[mt][nt][3];
        }
    __syncwarp();
    float* fp = g_f + (size_t)n * CM_ * HW_ + base + wm * 32;
    #pragma unroll
    for (int ol = 0; ol < 32; ++ol) {
        int o = wn * 32 + ol;
        float v = st[lane * 33 + ol] + conv_b[o];
        fp[(size_t)o * HW_ + lane] = fmaxf(v, 0.f);
    }
}

// ---------------- kernel 4: both dynamic depthwise convs (register-tiled) ----------------
// Block: (32-row chunk, c, n). Thread computes a 4-px vertical strip from s[8][5] regs.
__global__ __launch_bounds__(256) void dw_kernel(
    const float* __restrict__ adap_b, const float* __restrict__ atrous_b)
{
    __shared__ float sf[36][100];
    __shared__ float w5[25], w3[9];
    int t  = threadIdx.x;
    int rc = blockIdx.x;   // 0..2 (32-row chunks)
    int c  = blockIdx.y;
    int n  = blockIdx.z;
    int r0 = rc * 32;
    const float* fp = g_f + ((size_t)n * CM_ + c) * HW_;

    for (int idx = t; idx < 3600; idx += 256) {
        int i = idx / 100, j = idx - i * 100;
        int grow = r0 - 2 + i, gcol = j - 2;
        float v = 0.f;
        if (grow >= 0 && grow < H_ && gcol >= 0 && gcol < W_) v = fp[grow * W_ + gcol];
        sf[i][j] = v;
    }
    if (t < 25) w5[t] = g_wdyn[((size_t)n * CM_ + c) * 25 + t];
    if (t < 9)  w3[t] = g_watr[((size_t)n * CM_ + c) * 9 + t];
    __syncthreads();

    float ab  = adap_b[c];
    float atb = atrous_b[c];
    float* o0 = g_dw0 + ((size_t)n * CM_ + c) * HW_;
    float* o1 = g_dw1 + ((size_t)n * CM_ + c) * HW_;

    #pragma unroll
    for (int q = 0; q < 3; ++q) {
        int task = t + q * 256;            // 0..767: 8 row-groups x 96 cols
        int rg = task / 96, cc = task - rg * 96;
        float s[8][5];
        #pragma unroll
        for (int i = 0; i < 8; ++i)
            #pragma unroll
            for (int j = 0; j < 5; ++j)
                s[i][j] = sf[rg * 4 + i][cc + j];

        float a5[4] = {ab, ab, ab, ab};
        #pragma unroll
        for (int rr = 0; rr < 4; ++rr)
            #pragma unroll
            for (int i = 0; i < 5; ++i)
                #pragma unroll
                for (int j = 0; j < 5; ++j)
                    a5[rr] = fmaf(w5[i * 5 + j], s[rr + i][j], a5[rr]);

        float a3[4] = {atb, atb, atb, atb};
        #pragma unroll
        for (int rr = 0; rr < 4; ++rr)
            #pragma unroll
            for (int i = 0; i < 3; ++i)
                #pragma unroll
                for (int j = 0; j < 3; ++j)
                    a3[rr] = fmaf(w3[i * 3 + j], s[rr + 2 * i][2 * j], a3[rr]);

        int rbase = r0 + rg * 4;
        #pragma unroll
        for (int rr = 0; rr < 4; ++rr) {
            o0[(rbase + rr) * W_ + cc] = a5[rr];
            o1[(rbase + rr) * W_ + cc] = a3[rr];
        }
    }
}

// ---------------- kernel 5: fuse GEMM via tf32 mma ----------------
// Block tile: 128 px x 128 outs, K=64 in 2 slabs of 32.
// 8 warps: wm=warp&3 -> 32-px strip, wn=warp>>2 (0..1) -> 64-out strip.
__global__ __launch_bounds__(256) void fuse_mma(
    float* __restrict__ out,
    const float* __restrict__ fuse_w,
    const float* __restrict__ fuse_b)
{
    __shared__ float sm[8704];
    float* xs = sm;            // [32][136]
    float* wt = sm + 4352;     // [32][136]
    int t = threadIdx.x, lane = t & 31, warp = t >> 5;
    int gq = lane >> 2, gr = lane & 3;
    int n = blockIdx.y, br = blockIdx.z;
    int base = blockIdx.x * 128;
    int wm = warp & 3, wn = warp >> 2;
    const float* dwp = (br ? g_dw1 : g_dw0) + (size_t)n * CM_ * HW_ + base;

    float acc[2][8][4];
    #pragma unroll
    for (int a = 0; a < 2; a++)
        #pragma unroll
        for (int b = 0; b < 8; b++)
            #pragma unroll
            for (int c = 0; c < 4; c++) acc[a][b][c] = 0.f;

    for (int slab = 0; slab < 2; ++slab) {
        #pragma unroll
        for (int i = 0; i < 4; ++i) {
            int idx = t + i * 256;
            int r = idx >> 5, c4 = idx & 31;
            float4 v = *(const float4*)(dwp + (size_t)(slab * 32 + r) * HW_ + c4 * 4);
            float4 w;
            w.x = f2tf(v.x); w.y = f2tf(v.y); w.z = f2tf(v.z); w.w = f2tf(v.w);
            *(float4*)(xs + r * 136 + c4 * 4) = w;
        }
        #pragma unroll
        for (int i = 0; i < 16; ++i) {
            int idx = t + i * 256;
            int k = idx & 31, o = idx >> 5;
            wt[k * 136 + o] = f2tf(fuse_w[o * 64 + slab * 32 + k]);
        }
        __syncthreads();
        #pragma unroll
        for (int kk = 0; kk < 4; ++kk) {
            int k0 = kk * 8;
            uint32_t a[2][4];
            #pragma unroll
            for (int mt = 0; mt < 2; ++mt) {
                int px = wm * 32 + mt * 16 + gq;
                a[mt][0] = __float_as_uint(xs[(k0 + gr) * 136 + px]);
                a[mt][1] = __float_as_uint(xs[(k0 + gr) * 136 + px + 8]);
                a[mt][2] = __float_as_uint(xs[(k0 + gr + 4) * 136 + px]);
                a[mt][3] = __float_as_uint(xs[(k0 + gr + 4) * 136 + px + 8]);
            }
            #pragma unroll
            for (int nt = 0; nt < 8; ++nt) {
                int o = wn * 64 + nt * 8 + gq;
                uint32_t b0 = __float_as_uint(wt[(k0 + gr) * 136 + o]);
                uint32_t b1 = __float_as_uint(wt[(k0 + gr + 4) * 136 + o]);
                mma8(acc[0][nt], a[0], b0, b1);
                mma8(acc[1][nt], a[1], b0, b1);
            }
        }
        __syncthreads();
    }

    // epilogue: two 32-out halves per warp through the staging tile
    float* st = sm + warp * 1056;
    float* yp = out + ((size_t)n * 256 + (size_t)br * 128 + (size_t)wn * 64) * HW_ + base + wm * 32;
    #pragma unroll
    for (int h = 0; h < 2; ++h) {
        __syncwarp();
        #pragma unroll
        for (int mt = 0; mt < 2; ++mt)
            #pragma unroll
            for (int n4 = 0; n4 < 4; ++n4) {
                int nt = h * 4 + n4;
                int pr = mt * 16 + gq, oc = n4 * 8 + 2 * gr;
                st[pr * 33 + oc]           = acc[mt][nt][0];
                st[pr * 33 + oc + 1]       = acc[mt][nt][1];
                st[(pr + 8) * 33 + oc]     = acc[mt][nt][2];
                st[(pr + 8) * 33 + oc + 1] = acc[mt][nt][3];
            }
        __syncwarp();
        #pragma unroll
        for (int ol = 0; ol < 32; ++ol) {
            int og = h * 32 + ol;
            float v = st[lane * 33 + ol] + fuse_b[wn * 64 + og];
            yp[(size_t)og * HW_ + lane] = v;
        }
    }
}

// ---------------- launcher ----------------
extern "C" void kernel_launch(void* const* d_in, const int* in_sizes, int n_in,
                              void* d_out, int out_size) {
    const float* x        = (const float*)d_in[0];
    const float* conv_w   = (const float*)d_in[1];
    const float* conv_b   = (const float*)d_in[2];
    const float* ckw      = (const float*)d_in[3];
    const float* ckb      = (const float*)d_in[4];
    const float* ck2w     = (const float*)d_in[5];
    const float* ck2b     = (const float*)d_in[6];
    const float* kw       = (const float*)d_in[7];
    const float* kb       = (const float*)d_in[8];
    const float* k2w      = (const float*)d_in[9];
    const float* k2b      = (const float*)d_in[10];
    const float* fuse_w   = (const float*)d_in[11];
    const float* fuse_b   = (const float*)d_in[12];
    const float* adap_b   = (const float*)d_in[13];
    const float* atrous_b = (const float*)d_in[14];
    float* out = (float*)d_out;

    mean_kernel<<<N_ * C_, 256>>>(x);
    weights_kernel<<<N_, 256>>>(conv_w, conv_b, ckw, ckb, ck2w, ck2b, kw, kb, k2w, k2b);
    conv1_mma<<<dim3(HW_ / 128, N_), 256>>>(x, conv_w, conv_b);
    dw_kernel<<<dim3(3, CM_, N_), 256>>>(adap_b, atrous_b);
    fuse_mma<<<dim3(HW_ / 128, N_, 2), 256>>>(out, fuse_w, fuse_b);
}